// round 6
// baseline (speedup 1.0000x reference)
#include <cuda_runtime.h>
#include <math.h>

#define NB 4
#define NL 4096
#define DIMQ 7168
#define NH 128
#define NK 128
#define DC 512
#define DCQ 1536
#define NR 64
#define LSPLIT 16

// ---------------- scratch ----------------
__device__ float g_qhk[NB * NH * NK];
__device__ float g_qbig[NB * NH * DCQ];
__device__ float g_qr[NB * NH * NR];
__device__ float g_vq[NB * DC * NH];          // [b][d][h]
__device__ float g_kv[(size_t)NB * NL * DC];  // [b][l][d]
__device__ float g_kvT[(size_t)NB * DC * NL]; // [b][d][l]
__device__ float g_scT[(size_t)NB * NL * NH]; // [b][l][h] scores -> attn in place
__device__ float g_pm[NB * 32 * NH];
__device__ float g_ps[NB * 32 * NH];
__device__ float2 g_minv[NB * NH];
__device__ float g_part[(size_t)LSPLIT * NB * NH * DC];
__device__ float g_ctxc[NB * NH * DC];
__device__ float g_ctxlat[NB * NH * NK];
__device__ float g_invf[256];

#define FMA2(c, a, b) asm("fma.rn.f32x2 %0, %1, %2, %0;" : "+l"(c) : "l"(a), "l"(b))

__global__ void k_init_invf() {
    int t = threadIdx.x;
    g_invf[t] = (float)exp(-9.210340371976184 * (double)t / 256.0);
}

// ---------------- RoPE: writes g_kv [b][l][d] and g_kvT [b][d][l] ----------------
__global__ void k_rope2(const float* __restrict__ kvc) {
    extern __shared__ float s[];  // [512][33]
    int b = blockIdx.y, l0 = blockIdx.x * 32;
    int tid = threadIdx.x;
    // load raw, transposed into smem
    for (int i = tid; i < 32 * 512; i += 256) {
        int l = i >> 9, d = i & 511;
        s[d * 33 + l] = kvc[((size_t)(b * NL) + l0 + l) * DC + d];
    }
    __syncthreads();
    // pass A: write g_kv (lanes vary d -> coalesced)
    for (int i = tid; i < 32 * 512; i += 256) {
        int d = i & 511, l = i >> 9;
        float x1 = s[d * 33 + l];
        int p = (d < 256) ? d + 256 : d - 256;
        float x2 = s[p * 33 + l];
        float th = (float)(l0 + l) * g_invf[d >> 1];
        float sn, cs;
        sincosf(th, &sn, &cs);
        float y = x1 * cs + ((d < 256) ? -x2 : x2) * sn;
        g_kv[((size_t)(b * NL) + l0 + l) * DC + d] = y;
    }
    // pass B: write g_kvT (lanes vary l -> coalesced)
    for (int i = tid; i < 32 * 512; i += 256) {
        int l = i & 31, d = i >> 5;
        float x1 = s[d * 33 + l];
        int p = (d < 256) ? d + 256 : d - 256;
        float x2 = s[p * 33 + l];
        float th = (float)(l0 + l) * g_invf[d >> 1];
        float sn, cs;
        sincosf(th, &sn, &cs);
        float y = x1 * cs + ((d < 256) ? -x2 : x2) * sn;
        g_kvT[((size_t)(b * DC) + d) * NL + l0 + l] = y;
    }
}

// ---------------- register-blocked GEMV: Y[b,row] = dot(X[b,:], W[row,:]) ----------------
// 8 warps/block, R rows per warp, X direct through L1
template <int COLS, int R>
__global__ __launch_bounds__(256) void k_gemv_v2(const float* __restrict__ W,
                                                 const float* __restrict__ X,
                                                 float* __restrict__ Y, int rows) {
    const int tid = threadIdx.x;
    const int lane = tid & 31, warp = tid >> 5;
    const int row0 = (blockIdx.x * 8 + warp) * R;
    const float4* __restrict__ X4 = reinterpret_cast<const float4*>(X);
    const float4* __restrict__ W4 = reinterpret_cast<const float4*>(W);
    float acc[R][4];
    #pragma unroll
    for (int r = 0; r < R; r++)
        #pragma unroll
        for (int q = 0; q < 4; q++) acc[r][q] = 0.f;

    #pragma unroll 2
    for (int j = lane; j < COLS / 4; j += 32) {
        float4 x0 = X4[0 * (COLS / 4) + j];
        float4 x1 = X4[1 * (COLS / 4) + j];
        float4 x2 = X4[2 * (COLS / 4) + j];
        float4 x3 = X4[3 * (COLS / 4) + j];
        #pragma unroll
        for (int r = 0; r < R; r++) {
            float4 w = W4[(size_t)(row0 + r) * (COLS / 4) + j];
            acc[r][0] += w.x * x0.x + w.y * x0.y + w.z * x0.z + w.w * x0.w;
            acc[r][1] += w.x * x1.x + w.y * x1.y + w.z * x1.z + w.w * x1.w;
            acc[r][2] += w.x * x2.x + w.y * x2.y + w.z * x2.z + w.w * x2.w;
            acc[r][3] += w.x * x3.x + w.y * x3.y + w.z * x3.z + w.w * x3.w;
        }
    }
    #pragma unroll
    for (int r = 0; r < R; r++) {
        #pragma unroll
        for (int q = 0; q < 4; q++) {
            float v = acc[r][q];
            #pragma unroll
            for (int o = 16; o; o >>= 1) v += __shfl_down_sync(0xffffffffu, v, o);
            if (lane == 0) Y[q * rows + row0 + r] = v;
        }
    }
}

// ---------------- q_big[b,h,q] = sum_k q_hk[b,h,k] * w_kc_q[h,k,q] ----------------
__global__ __launch_bounds__(192) void k_qbig2(const float* __restrict__ w) {
    int h = blockIdx.x;
    int tid = threadIdx.x;
    __shared__ float qs[NB][NK];
    for (int i = tid; i < NB * NK; i += 192)
        qs[i >> 7][i & 127] = g_qhk[(i >> 7) * (NH * NK) + h * NK + (i & 127)];
    __syncthreads();
    int q = blockIdx.y * 768 + tid * 4;
    const float4* wp = reinterpret_cast<const float4*>(w + (size_t)h * NK * DCQ + q);
    float4 a[4];
    #pragma unroll
    for (int b = 0; b < 4; b++) a[b] = make_float4(0.f, 0.f, 0.f, 0.f);
    #pragma unroll 8
    for (int k = 0; k < NK; k++) {
        float4 wv = wp[(size_t)k * (DCQ / 4)];
        #pragma unroll
        for (int b = 0; b < 4; b++) {
            float qv = qs[b][k];
            a[b].x += qv * wv.x; a[b].y += qv * wv.y;
            a[b].z += qv * wv.z; a[b].w += qv * wv.w;
        }
    }
    #pragma unroll
    for (int b = 0; b < 4; b++)
        *reinterpret_cast<float4*>(g_qbig + b * (NH * DCQ) + h * DCQ + q) = a[b];
}

// ---------------- q_r[b,h,r] = sum_q q_big[b,h,q] * W_qr[h,q,r] ----------------
__global__ __launch_bounds__(256) void k_qr(const float* __restrict__ w) {
    int h = blockIdx.x;
    __shared__ float qs[NB][DCQ];
    __shared__ float part[4][NB][NR];
    for (int i = threadIdx.x; i < NB * DCQ; i += 256) {
        int b = i / DCQ, q = i % DCQ;
        qs[b][q] = g_qbig[b * (NH * DCQ) + h * DCQ + q];
    }
    __syncthreads();
    int qc = threadIdx.x >> 6, r = threadIdx.x & 63;
    float a0 = 0.f, a1 = 0.f, a2 = 0.f, a3 = 0.f;
    const float* wp = w + (size_t)h * DCQ * NR;
    int q0 = qc * 384;
    for (int q = q0; q < q0 + 384; q++) {
        float wv = wp[q * NR + r];
        a0 += qs[0][q] * wv; a1 += qs[1][q] * wv;
        a2 += qs[2][q] * wv; a3 += qs[3][q] * wv;
    }
    part[qc][0][r] = a0; part[qc][1][r] = a1;
    part[qc][2][r] = a2; part[qc][3][r] = a3;
    __syncthreads();
    if (qc == 0) {
        #pragma unroll
        for (int b = 0; b < NB; b++)
            g_qr[b * (NH * NR) + h * NR + r] =
                part[0][b][r] + part[1][b][r] + part[2][b][r] + part[3][b][r];
    }
}

// ---------------- v_q[b,d,h] = sum_r W_kr[h,d,r] * q_r[b,h,r] ----------------
__global__ __launch_bounds__(256) void k_vq(const float* __restrict__ w) {
    int h = blockIdx.x;
    __shared__ float qs[NB][NR];
    for (int i = threadIdx.x; i < NB * NR; i += 256)
        qs[i >> 6][i & 63] = g_qr[(i >> 6) * (NH * NR) + h * NR + (i & 63)];
    __syncthreads();
    for (int d = threadIdx.x; d < DC; d += 256) {
        const float4* wp = reinterpret_cast<const float4*>(w + ((size_t)h * DC + d) * NR);
        float a0 = 0.f, a1 = 0.f, a2 = 0.f, a3 = 0.f;
        #pragma unroll
        for (int rv = 0; rv < 16; rv++) {
            float4 wv = wp[rv];
            int r = rv * 4;
            a0 += wv.x * qs[0][r] + wv.y * qs[0][r + 1] + wv.z * qs[0][r + 2] + wv.w * qs[0][r + 3];
            a1 += wv.x * qs[1][r] + wv.y * qs[1][r + 1] + wv.z * qs[1][r + 2] + wv.w * qs[1][r + 3];
            a2 += wv.x * qs[2][r] + wv.y * qs[2][r + 1] + wv.z * qs[2][r + 2] + wv.w * qs[2][r + 3];
            a3 += wv.x * qs[3][r] + wv.y * qs[3][r + 1] + wv.z * qs[3][r + 2] + wv.w * qs[3][r + 3];
        }
        g_vq[0 * (DC * NH) + d * NH + h] = a0;
        g_vq[1 * (DC * NH) + d * NH + h] = a1;
        g_vq[2 * (DC * NH) + d * NH + h] = a2;
        g_vq[3 * (DC * NH) + d * NH + h] = a3;
    }
}

// ---------------- scores GEMM: scT[b,l,h] = sum_d vq[b,d,h] * kvT[b,d,l] ----------------
// tile 128h x 128l, k-chunk 32, f32x2 packed FMA, A duplicated pairs in smem
__global__ __launch_bounds__(256) void k_scores() {
    extern __shared__ float sm[];
    float* As2 = sm;             // [32][256]  (vq, each h duplicated)
    float* Bs = sm + 32 * 256;   // [32][128]  (kvT)
    int b = blockIdx.y, l0 = blockIdx.x * 128;
    int tid = threadIdx.x, tx = tid & 15, ty = tid >> 4;
    unsigned long long acc[8][4];
    #pragma unroll
    for (int i = 0; i < 8; i++)
        #pragma unroll
        for (int j = 0; j < 4; j++) acc[i][j] = 0ULL;

    for (int k0 = 0; k0 < DC; k0 += 32) {
        __syncthreads();
        for (int i = tid; i < 32 * 128; i += 256) {
            int k = i >> 7, h = i & 127;
            float v = g_vq[(b * DC + k0 + k) * NH + h];
            reinterpret_cast<float2*>(As2 + k * 256)[h] = make_float2(v, v);
        }
        for (int i = tid; i < 32 * 128; i += 256) {
            int k = i >> 7, ll = i & 127;
            Bs[k * 128 + ll] = g_kvT[((size_t)(b * DC) + k0 + k) * NL + l0 + ll];
        }
        __syncthreads();
        #pragma unroll 4
        for (int k = 0; k < 32; k++) {
            ulonglong2 a01 = *reinterpret_cast<ulonglong2*>(As2 + k * 256 + ty * 16);
            ulonglong2 a23 = *reinterpret_cast<ulonglong2*>(As2 + k * 256 + ty * 16 + 4);
            ulonglong2 a45 = *reinterpret_cast<ulonglong2*>(As2 + k * 256 + ty * 16 + 8);
            ulonglong2 a67 = *reinterpret_cast<ulonglong2*>(As2 + k * 256 + ty * 16 + 12);
            ulonglong2 b01 = *reinterpret_cast<ulonglong2*>(Bs + k * 128 + tx * 8);
            ulonglong2 b23 = *reinterpret_cast<ulonglong2*>(Bs + k * 128 + tx * 8 + 4);
            unsigned long long av[8] = {a01.x, a01.y, a23.x, a23.y, a45.x, a45.y, a67.x, a67.y};
            unsigned long long bv[4] = {b01.x, b01.y, b23.x, b23.y};
            #pragma unroll
            for (int i = 0; i < 8; i++)
                #pragma unroll
                for (int j = 0; j < 4; j++) FMA2(acc[i][j], av[i], bv[j]);
        }
    }
    // epilogue: transpose via smem [128l][132]
    __syncthreads();
    #pragma unroll
    for (int i = 0; i < 8; i++)
        #pragma unroll
        for (int j = 0; j < 4; j++) {
            float2 f = *reinterpret_cast<float2*>(&acc[i][j]);
            sm[(tx * 8 + 2 * j) * 132 + ty * 8 + i] = f.x;
            sm[(tx * 8 + 2 * j + 1) * 132 + ty * 8 + i] = f.y;
        }
    __syncthreads();
    for (int i = tid; i < 128 * 128; i += 256) {
        int l = i >> 7, h = i & 127;
        g_scT[((size_t)(b * NL) + l0 + l) * NH + h] = sm[l * 132 + h];
    }
}

// ---------------- softmax on [l][h]: partial -> finalize -> normalize ----------------
__global__ __launch_bounds__(256) void k_sm_part() {
    int lc = blockIdx.x, b = blockIdx.y;
    int tid = threadIdx.x, h = tid & 127, lg = tid >> 7;
    __shared__ float smm[2][128], sms[2][128];
    float m = -3.4e38f, s = 0.f;
    for (int it = 0; it < 64; it++) {
        int l = lc * 128 + lg + 2 * it;
        float x = g_scT[((size_t)(b * NL) + l) * NH + h];
        float nm = fmaxf(m, x);
        s = s * __expf(m - nm) + __expf(x - nm);
        m = nm;
    }
    smm[lg][h] = m; sms[lg][h] = s;
    __syncthreads();
    if (lg == 0) {
        float m0 = smm[0][h], m1 = smm[1][h];
        float nm = fmaxf(m0, m1);
        float ns = sms[0][h] * __expf(m0 - nm) + sms[1][h] * __expf(m1 - nm);
        g_pm[(b * 32 + lc) * NH + h] = nm;
        g_ps[(b * 32 + lc) * NH + h] = ns;
    }
}

__global__ void k_sm_fin() {
    int b = blockIdx.x, h = threadIdx.x;
    float m = -3.4e38f, s = 0.f;
    for (int c = 0; c < 32; c++) {
        float mc = g_pm[(b * 32 + c) * NH + h];
        float sc = g_ps[(b * 32 + c) * NH + h];
        float nm = fmaxf(m, mc);
        s = s * __expf(m - nm) + sc * __expf(mc - nm);
        m = nm;
    }
    g_minv[b * NH + h] = make_float2(m, 1.f / s);
}

__global__ __launch_bounds__(256) void k_sm_norm() {
    int lc = blockIdx.x, b = blockIdx.y;
    int tid = threadIdx.x, h = tid & 127, lg = tid >> 7;
    float2 mi = g_minv[b * NH + h];
    for (int it = 0; it < 64; it++) {
        int l = lc * 128 + lg + 2 * it;
        size_t idx = ((size_t)(b * NL) + l) * NH + h;
        g_scT[idx] = __expf(g_scT[idx] - mi.x) * mi.y;
    }
}

// ---------------- ctx GEMM: part[ls,b,h,d] = sum_l attnT[b,l,h] * kv[b,l,d] ----------------
__global__ __launch_bounds__(256) void k_ctx() {
    extern __shared__ float sm[];
    float* As2 = sm;            // [32][256] attn dup
    float* Bs = sm + 32 * 256;  // [32][128] kv
    int ls = blockIdx.x, d0 = blockIdx.y * 128, b = blockIdx.z;
    int lb = ls * (NL / LSPLIT);
    int tid = threadIdx.x, tx = tid & 15, ty = tid >> 4;
    unsigned long long acc[8][4];
    #pragma unroll
    for (int i = 0; i < 8; i++)
        #pragma unroll
        for (int j = 0; j < 4; j++) acc[i][j] = 0ULL;

    for (int k0 = 0; k0 < NL / LSPLIT; k0 += 32) {
        __syncthreads();
        for (int i = tid; i < 32 * 128; i += 256) {
            int k = i >> 7, h = i & 127;
            float v = g_scT[((size_t)(b * NL) + lb + k0 + k) * NH + h];
            reinterpret_cast<float2*>(As2 + k * 256)[h] = make_float2(v, v);
        }
        for (int i = tid; i < 32 * 128; i += 256) {
            int k = i >> 7, dd = i & 127;
            Bs[k * 128 + dd] = g_kv[((size_t)(b * NL) + lb + k0 + k) * DC + d0 + dd];
        }
        __syncthreads();
        #pragma unroll 4
        for (int k = 0; k < 32; k++) {
            ulonglong2 a01 = *reinterpret_cast<ulonglong2*>(As2 + k * 256 + ty * 16);
            ulonglong2 a23 = *reinterpret_cast<ulonglong2*>(As2 + k * 256 + ty * 16 + 4);
            ulonglong2 a45 = *reinterpret_cast<ulonglong2*>(As2 + k * 256 + ty * 16 + 8);
            ulonglong2 a67 = *reinterpret_cast<ulonglong2*>(As2 + k * 256 + ty * 16 + 12);
            ulonglong2 b01 = *reinterpret_cast<ulonglong2*>(Bs + k * 128 + tx * 8);
            ulonglong2 b23 = *reinterpret_cast<ulonglong2*>(Bs + k * 128 + tx * 8 + 4);
            unsigned long long av[8] = {a01.x, a01.y, a23.x, a23.y, a45.x, a45.y, a67.x, a67.y};
            unsigned long long bv[4] = {b01.x, b01.y, b23.x, b23.y};
            #pragma unroll
            for (int i = 0; i < 8; i++)
                #pragma unroll
                for (int j = 0; j < 4; j++) FMA2(acc[i][j], av[i], bv[j]);
        }
    }
    // epilogue: direct coalesced float4 stores
    #pragma unroll
    for (int i = 0; i < 8; i++) {
        float2 f0 = *reinterpret_cast<float2*>(&acc[i][0]);
        float2 f1 = *reinterpret_cast<float2*>(&acc[i][1]);
        float2 f2 = *reinterpret_cast<float2*>(&acc[i][2]);
        float2 f3 = *reinterpret_cast<float2*>(&acc[i][3]);
        int h = ty * 8 + i;
        float* dst = g_part + (((size_t)ls * NB + b) * NH + h) * DC + d0 + tx * 8;
        reinterpret_cast<float4*>(dst)[0] = make_float4(f0.x, f0.y, f1.x, f1.y);
        reinterpret_cast<float4*>(dst)[1] = make_float4(f2.x, f2.y, f3.x, f3.y);
    }
}

__global__ __launch_bounds__(256) void k_ctx_red() {
    int i = blockIdx.x * 256 + threadIdx.x;
    float s = 0.f;
    #pragma unroll
    for (int ls = 0; ls < LSPLIT; ls++) s += g_part[(size_t)ls * (NB * NH * DC) + i];
    g_ctxc[i] = s;
}

// ---------------- ctx_lat[b,h,k] = sum_d ctx_c[b,h,d] * w_kc_kv[h,k,d] ----------------
__global__ __launch_bounds__(256) void k_ctxlat(const float* __restrict__ w) {
    int h = blockIdx.x;
    __shared__ float cs[NB][DC];
    int tid = threadIdx.x;
    for (int i = tid; i < NB * DC; i += 256) {
        int bb = i >> 9, d = i & 511;
        cs[bb][d] = g_ctxc[bb * (NH * DC) + h * DC + d];
    }
    __syncthreads();
    int lane = tid & 31, warp = tid >> 5;
    int k = blockIdx.y * 8 + warp;
    const float* wp = w + ((size_t)h * NK + k) * DC;
    float a0 = 0.f, a1 = 0.f, a2 = 0.f, a3 = 0.f;
    for (int d = lane; d < DC; d += 32) {
        float wv = wp[d];
        a0 += cs[0][d] * wv; a1 += cs[1][d] * wv;
        a2 += cs[2][d] * wv; a3 += cs[3][d] * wv;
    }
    #pragma unroll
    for (int o = 16; o; o >>= 1) {
        a0 += __shfl_down_sync(0xffffffffu, a0, o);
        a1 += __shfl_down_sync(0xffffffffu, a1, o);
        a2 += __shfl_down_sync(0xffffffffu, a2, o);
        a3 += __shfl_down_sync(0xffffffffu, a3, o);
    }
    if (lane == 0) {
        g_ctxlat[0 * (NH * NK) + h * NK + k] = a0;
        g_ctxlat[1 * (NH * NK) + h * NK + k] = a1;
        g_ctxlat[2 * (NH * NK) + h * NK + k] = a2;
        g_ctxlat[3 * (NH * NK) + h * NK + k] = a3;
    }
}

extern "C" void kernel_launch(void* const* d_in, const int* in_sizes, int n_in,
                              void* d_out, int out_size) {
    const float* hidden_q = (const float*)d_in[0];
    const float* kv_c     = (const float*)d_in[1];
    const float* Wq       = (const float*)d_in[2];
    const float* w_kc_q   = (const float*)d_in[3];
    const float* w_kc_kv  = (const float*)d_in[4];
    const float* W_qr     = (const float*)d_in[5];
    const float* W_kr     = (const float*)d_in[6];
    const float* Wout     = (const float*)d_in[7];
    float* out = (float*)d_out;

    void* qhk_p = nullptr;
    void* ctxlat_p = nullptr;
    cudaGetSymbolAddress(&qhk_p, g_qhk);
    cudaGetSymbolAddress(&ctxlat_p, g_ctxlat);

    cudaFuncSetAttribute(k_rope2, cudaFuncAttributeMaxDynamicSharedMemorySize, 512 * 33 * 4);
    cudaFuncSetAttribute(k_scores, cudaFuncAttributeMaxDynamicSharedMemorySize, 128 * 132 * 4);
    cudaFuncSetAttribute(k_ctx, cudaFuncAttributeMaxDynamicSharedMemorySize, 48 * 1024);

    k_init_invf<<<1, 256>>>();
    k_rope2<<<dim3(NL / 32, NB), 256, 512 * 33 * 4>>>(kv_c);

    // query chain
    k_gemv_v2<DIMQ, 8><<<(NH * NK) / 64, 256>>>(Wq, hidden_q, (float*)qhk_p, NH * NK);
    k_qbig2<<<dim3(NH, 2), 192>>>(w_kc_q);
    k_qr<<<NH, 256>>>(W_qr);
    k_vq<<<NH, 256>>>(W_kr);

    // attention
    k_scores<<<dim3(NL / 128, NB), 256, 128 * 132 * 4>>>();
    k_sm_part<<<dim3(32, NB), 256>>>();
    k_sm_fin<<<NB, 128>>>();
    k_sm_norm<<<dim3(32, NB), 256>>>();
    k_ctx<<<dim3(LSPLIT, 4, NB), 256, 48 * 1024>>>();
    k_ctx_red<<<(NB * NH * DC) / 256, 256>>>();

    // output chain
    k_ctxlat<<<dim3(NH, NK / 8), 256>>>(w_kc_kv);
    k_gemv_v2<NH * NK, 8><<<DIMQ / 64, 256>>>(Wout, (const float*)ctxlat_p, out, DIMQ);
}

// round 7
// speedup vs baseline: 1.2369x; 1.2369x over previous
#include <cuda_runtime.h>
#include <math.h>

#define NB 4
#define NL 4096
#define DIMQ 7168
#define NH 128
#define NK 128
#define DC 512
#define DCQ 1536
#define NR 64

// ---------------- scratch (static device globals; no allocation) ----------------
__device__ float g_qhk[NB * NH * NK];
__device__ float g_qbigp[4 * NB * NH * DCQ];   // k-split partials
__device__ float g_qbig[NB * NH * DCQ];
__device__ float g_qr[NB * NH * NR];
__device__ float g_vq[NB * DC * NH];           // [b][d][h]
__device__ float g_kv[(size_t)NB * NL * DC];   // RoPE'd kv cache
__device__ float g_sc[NB * NH * NL];           // scores -> attn (in place)
__device__ float g_part[8 * NB * NH * DC];
__device__ float g_ctxc[NB * NH * DC];
__device__ float g_ctxlat[NB * NH * NK];
__device__ float g_invf[256];

#define FMA2(c, a, b) asm("fma.rn.f32x2 %0, %1, %2, %0;" : "+l"(c) : "l"(a), "l"(b))

__device__ __forceinline__ unsigned long long pack2(float f) {
    unsigned long long u;
    asm("mov.b64 %0, {%1, %1};" : "=l"(u) : "f"(f));
    return u;
}

// ---------------- inv-freq table ----------------
__global__ void k_init_invf() {
    int t = threadIdx.x;
    g_invf[t] = (float)exp(-9.210340371976184 * (double)t / 256.0);
}

// ---------------- RoPE ----------------
__global__ void k_rope(const float* __restrict__ kvc) {
    int bl = blockIdx.x;
    int l = bl & (NL - 1);
    const float* x = kvc + (size_t)bl * DC;
    float* y = g_kv + (size_t)bl * DC;
    int d = threadIdx.x;
    float x1 = x[d], x2 = x[d + 256];
    int j = d >> 1;
    float th1 = (float)l * g_invf[j];
    float th2 = (float)l * g_invf[128 + j];
    float s1, c1, s2, c2;
    sincosf(th1, &s1, &c1);
    sincosf(th2, &s2, &c2);
    y[d]       = x1 * c1 - x2 * s1;
    y[d + 256] = x2 * c2 + x1 * s2;
}

// ---------------- generic 4-row GEMV (R1) ----------------
template <int COLS, int CHUNK>
__global__ __launch_bounds__(256) void k_gemv4(const float* __restrict__ W,
                                               const float* __restrict__ X,
                                               float* __restrict__ Y, int rows) {
    __shared__ float4 xs[NB][CHUNK / 4];
    const int tid = threadIdx.x;
    const int lane = tid & 31, warp = tid >> 5;
    const int row = blockIdx.x * 8 + warp;
    float a0 = 0.f, a1 = 0.f, a2 = 0.f, a3 = 0.f;
    for (int j0 = 0; j0 < COLS; j0 += CHUNK) {
        __syncthreads();
        for (int i = tid; i < NB * (CHUNK / 4); i += 256) {
            int b = i / (CHUNK / 4), j = i % (CHUNK / 4);
            xs[b][j] = reinterpret_cast<const float4*>(X + (size_t)b * COLS + j0)[j];
        }
        __syncthreads();
        const float4* w4 = reinterpret_cast<const float4*>(W + (size_t)row * COLS + j0);
        #pragma unroll 4
        for (int j = lane; j < CHUNK / 4; j += 32) {
            float4 w = w4[j];
            float4 v0 = xs[0][j], v1 = xs[1][j], v2 = xs[2][j], v3 = xs[3][j];
            a0 += w.x * v0.x + w.y * v0.y + w.z * v0.z + w.w * v0.w;
            a1 += w.x * v1.x + w.y * v1.y + w.z * v1.z + w.w * v1.w;
            a2 += w.x * v2.x + w.y * v2.y + w.z * v2.z + w.w * v2.w;
            a3 += w.x * v3.x + w.y * v3.y + w.z * v3.z + w.w * v3.w;
        }
    }
    #pragma unroll
    for (int o = 16; o; o >>= 1) {
        a0 += __shfl_down_sync(0xffffffffu, a0, o);
        a1 += __shfl_down_sync(0xffffffffu, a1, o);
        a2 += __shfl_down_sync(0xffffffffu, a2, o);
        a3 += __shfl_down_sync(0xffffffffu, a3, o);
    }
    if (lane == 0) {
        Y[0 * rows + row] = a0;
        Y[1 * rows + row] = a1;
        Y[2 * rows + row] = a2;
        Y[3 * rows + row] = a3;
    }
}

// ---------------- q_big k-split: part[kc][b,h,q] = sum_{k in chunk} qhk*w ----------------
__global__ __launch_bounds__(192) void k_qbig3(const float* __restrict__ w) {
    int h = blockIdx.x, qc = blockIdx.y, kc = blockIdx.z;
    int tid = threadIdx.x;
    __shared__ float qs[NB][32];
    for (int i = tid; i < NB * 32; i += 192)
        qs[i >> 5][i & 31] = g_qhk[(i >> 5) * (NH * NK) + h * NK + kc * 32 + (i & 31)];
    __syncthreads();
    int q = qc * 768 + tid * 4;
    const float4* wp = reinterpret_cast<const float4*>(
        w + ((size_t)h * NK + kc * 32) * DCQ + q);
    float4 a[4];
    #pragma unroll
    for (int b = 0; b < 4; b++) a[b] = make_float4(0.f, 0.f, 0.f, 0.f);
    #pragma unroll 8
    for (int k = 0; k < 32; k++) {
        float4 wv = wp[(size_t)k * (DCQ / 4)];
        #pragma unroll
        for (int b = 0; b < 4; b++) {
            float qv = qs[b][k];
            a[b].x += qv * wv.x; a[b].y += qv * wv.y;
            a[b].z += qv * wv.z; a[b].w += qv * wv.w;
        }
    }
    #pragma unroll
    for (int b = 0; b < 4; b++)
        *reinterpret_cast<float4*>(g_qbigp + (size_t)kc * (NB * NH * DCQ) +
                                   b * (NH * DCQ) + h * DCQ + q) = a[b];
}

__global__ __launch_bounds__(256) void k_qbig_red() {
    int i = blockIdx.x * 1024 + threadIdx.x * 4;
    const int N = NB * NH * DCQ;
    float4 s0 = *reinterpret_cast<float4*>(g_qbigp + i);
    float4 s1 = *reinterpret_cast<float4*>(g_qbigp + N + i);
    float4 s2 = *reinterpret_cast<float4*>(g_qbigp + 2 * N + i);
    float4 s3 = *reinterpret_cast<float4*>(g_qbigp + 3 * N + i);
    *reinterpret_cast<float4*>(g_qbig + i) =
        make_float4(s0.x + s1.x + s2.x + s3.x, s0.y + s1.y + s2.y + s3.y,
                    s0.z + s1.z + s2.z + s3.z, s0.w + s1.w + s2.w + s3.w);
}

// ---------------- q_r (R1) ----------------
__global__ __launch_bounds__(256) void k_qr(const float* __restrict__ w) {
    int h = blockIdx.x;
    __shared__ float qs[NB][DCQ];
    __shared__ float part[4][NB][NR];
    for (int i = threadIdx.x; i < NB * DCQ; i += 256) {
        int b = i / DCQ, q = i % DCQ;
        qs[b][q] = g_qbig[b * (NH * DCQ) + h * DCQ + q];
    }
    __syncthreads();
    int qc = threadIdx.x >> 6, r = threadIdx.x & 63;
    float a0 = 0.f, a1 = 0.f, a2 = 0.f, a3 = 0.f;
    const float* wp = w + (size_t)h * DCQ * NR;
    int q0 = qc * 384;
    for (int q = q0; q < q0 + 384; q++) {
        float wv = wp[q * NR + r];
        a0 += qs[0][q] * wv; a1 += qs[1][q] * wv;
        a2 += qs[2][q] * wv; a3 += qs[3][q] * wv;
    }
    part[qc][0][r] = a0; part[qc][1][r] = a1;
    part[qc][2][r] = a2; part[qc][3][r] = a3;
    __syncthreads();
    if (qc == 0) {
        #pragma unroll
        for (int b = 0; b < NB; b++)
            g_qr[b * (NH * NR) + h * NR + r] =
                part[0][b][r] + part[1][b][r] + part[2][b][r] + part[3][b][r];
    }
}

// ---------------- v_q (R1) ----------------
__global__ __launch_bounds__(256) void k_vq(const float* __restrict__ w) {
    int h = blockIdx.x;
    __shared__ float qs[NB][NR];
    for (int i = threadIdx.x; i < NB * NR; i += 256)
        qs[i >> 6][i & 63] = g_qr[(i >> 6) * (NH * NR) + h * NR + (i & 63)];
    __syncthreads();
    for (int d = threadIdx.x; d < DC; d += 256) {
        const float4* wp = reinterpret_cast<const float4*>(w + ((size_t)h * DC + d) * NR);
        float a0 = 0.f, a1 = 0.f, a2 = 0.f, a3 = 0.f;
        #pragma unroll
        for (int rv = 0; rv < 16; rv++) {
            float4 wv = wp[rv];
            int r = rv * 4;
            a0 += wv.x * qs[0][r] + wv.y * qs[0][r + 1] + wv.z * qs[0][r + 2] + wv.w * qs[0][r + 3];
            a1 += wv.x * qs[1][r] + wv.y * qs[1][r + 1] + wv.z * qs[1][r + 2] + wv.w * qs[1][r + 3];
            a2 += wv.x * qs[2][r] + wv.y * qs[2][r + 1] + wv.z * qs[2][r + 2] + wv.w * qs[2][r + 3];
            a3 += wv.x * qs[3][r] + wv.y * qs[3][r + 1] + wv.z * qs[3][r + 2] + wv.w * qs[3][r + 3];
        }
        g_vq[0 * (DC * NH) + d * NH + h] = a0;
        g_vq[1 * (DC * NH) + d * NH + h] = a1;
        g_vq[2 * (DC * NH) + d * NH + h] = a2;
        g_vq[3 * (DC * NH) + d * NH + h] = a3;
    }
}

// ---------------- scores (R1 structure, FMA2 inner) ----------------
__global__ __launch_bounds__(256) void k_scores() {
    int b = blockIdx.y, l0 = blockIdx.x * 32;
    __shared__ float sm[10240];   // vqs[64][128] @0, kvs[32][64] @8192
    int tid = threadIdx.x;
    int hq = tid & 31, lq = tid >> 5;
    unsigned long long acc2[2][4];
    #pragma unroll
    for (int p = 0; p < 2; p++)
        #pragma unroll
        for (int j = 0; j < 4; j++) acc2[p][j] = 0ULL;

    for (int d0 = 0; d0 < DC; d0 += 64) {
        __syncthreads();
        for (int i = tid; i < 8192; i += 256) {
            int d = i >> 7, hh = i & 127;
            sm[i] = g_vq[b * (DC * NH) + (d0 + d) * NH + hh];
        }
        for (int i = tid; i < 2048; i += 256) {
            int l = i >> 6, dd = i & 63;
            sm[8192 + i] = g_kv[((size_t)(b * NL) + l0 + l) * DC + d0 + dd];
        }
        __syncthreads();
        #pragma unroll 4
        for (int dd = 0; dd < 64; dd++) {
            ulonglong2 av = reinterpret_cast<ulonglong2*>(sm + dd * 128)[hq];
            #pragma unroll
            for (int j = 0; j < 4; j++) {
                unsigned long long kv2 = pack2(sm[8192 + (4 * lq + j) * 64 + dd]);
                FMA2(acc2[0][j], av.x, kv2);
                FMA2(acc2[1][j], av.y, kv2);
            }
        }
    }
    __syncthreads();
    #pragma unroll
    for (int p = 0; p < 2; p++)
        #pragma unroll
        for (int j = 0; j < 4; j++) {
            float2 f = *reinterpret_cast<float2*>(&acc2[p][j]);
            sm[(4 * hq + 2 * p) * 33 + 4 * lq + j] = f.x;
            sm[(4 * hq + 2 * p + 1) * 33 + 4 * lq + j] = f.y;
        }
    __syncthreads();
    for (int i = tid; i < 4096; i += 256) {
        int hh = i >> 5, l = i & 31;
        g_sc[((size_t)(b * NH) + hh) * NL + l0 + l] = sm[hh * 33 + l];
    }
}

// ---------------- softmax (R1) ----------------
__global__ __launch_bounds__(256) void k_softmax() {
    float* p = g_sc + (size_t)blockIdx.x * NL;
    __shared__ float red[8];
    int tid = threadIdx.x, lane = tid & 31, warp = tid >> 5;
    float m = -1e30f;
    for (int i = tid; i < NL; i += 256) m = fmaxf(m, p[i]);
    #pragma unroll
    for (int o = 16; o; o >>= 1) m = fmaxf(m, __shfl_xor_sync(0xffffffffu, m, o));
    if (lane == 0) red[warp] = m;
    __syncthreads();
    float bm = red[0];
    #pragma unroll
    for (int w = 1; w < 8; w++) bm = fmaxf(bm, red[w]);
    __syncthreads();
    float s = 0.f;
    for (int i = tid; i < NL; i += 256) {
        float e = expf(p[i] - bm);
        p[i] = e;
        s += e;
    }
    #pragma unroll
    for (int o = 16; o; o >>= 1) s += __shfl_xor_sync(0xffffffffu, s, o);
    if (lane == 0) red[warp] = s;
    __syncthreads();
    float bs = red[0];
    #pragma unroll
    for (int w = 1; w < 8; w++) bs += red[w];
    float inv = 1.0f / bs;
    for (int i = tid; i < NL; i += 256) p[i] *= inv;
}

// ---------------- ctx partials (R1 structure, FMA2 inner) ----------------
__global__ __launch_bounds__(256) void k_ctx() {
    int b = blockIdx.z;
    int h0 = blockIdx.y * 32;
    int ls = blockIdx.x >> 2;
    int d0 = (blockIdx.x & 3) * 128;
    int lbase = ls * 512;
    __shared__ float sm[5120];   // kvs[32][128] @0, atts[32][32] @4096
    int tid = threadIdx.x;
    int dq = tid & 31, hq = tid >> 5;
    unsigned long long acc2[4][2];
    #pragma unroll
    for (int j = 0; j < 4; j++)
        #pragma unroll
        for (int p = 0; p < 2; p++) acc2[j][p] = 0ULL;

    for (int lt = 0; lt < 512; lt += 32) {
        __syncthreads();
        for (int i = tid; i < 4096; i += 256) {
            int l = i >> 7, d = i & 127;
            sm[i] = g_kv[((size_t)(b * NL) + lbase + lt + l) * DC + d0 + d];
        }
        for (int i = tid; i < 1024; i += 256) {
            int hh = i >> 5, l = i & 31;
            sm[4096 + i] = g_sc[((size_t)(b * NH) + h0 + hh) * NL + lbase + lt + l];
        }
        __syncthreads();
        #pragma unroll 4
        for (int l = 0; l < 32; l++) {
            ulonglong2 kv2 = reinterpret_cast<ulonglong2*>(sm + l * 128)[dq];
            #pragma unroll
            for (int j = 0; j < 4; j++) {
                unsigned long long av2 = pack2(sm[4096 + (4 * hq + j) * 32 + l]);
                FMA2(acc2[j][0], av2, kv2.x);
                FMA2(acc2[j][1], av2, kv2.y);
            }
        }
    }
    __syncthreads();
    #pragma unroll
    for (int j = 0; j < 4; j++) {
        float2 f0 = *reinterpret_cast<float2*>(&acc2[j][0]);
        float2 f1 = *reinterpret_cast<float2*>(&acc2[j][1]);
        reinterpret_cast<float4*>(sm)[(4 * hq + j) * 33 + dq] =
            make_float4(f0.x, f0.y, f1.x, f1.y);
    }
    __syncthreads();
    for (int i = tid; i < 4096; i += 256) {
        int hh = i >> 7, d = i & 127;
        g_part[(((size_t)ls * NB + b) * NH + h0 + hh) * DC + d0 + d] = sm[hh * 132 + d];
    }
}

__global__ __launch_bounds__(256) void k_ctx_red() {
    int i = blockIdx.x * 256 + threadIdx.x;
    float s = 0.f;
    #pragma unroll
    for (int ls = 0; ls < 8; ls++) s += g_part[(size_t)ls * (NB * NH * DC) + i];
    g_ctxc[i] = s;
}

// ---------------- ctx_lat (R1) ----------------
__global__ __launch_bounds__(256) void k_ctxlat(const float* __restrict__ w) {
    int h = blockIdx.x;
    __shared__ float cs[NB][DC];
    int tid = threadIdx.x;
    for (int i = tid; i < NB * DC; i += 256) {
        int bb = i >> 9, d = i & 511;
        cs[bb][d] = g_ctxc[bb * (NH * DC) + h * DC + d];
    }
    __syncthreads();
    int lane = tid & 31, warp = tid >> 5;
    int k = blockIdx.y * 8 + warp;
    const float* wp = w + ((size_t)h * NK + k) * DC;
    float a0 = 0.f, a1 = 0.f, a2 = 0.f, a3 = 0.f;
    for (int d = lane; d < DC; d += 32) {
        float wv = wp[d];
        a0 += cs[0][d] * wv; a1 += cs[1][d] * wv;
        a2 += cs[2][d] * wv; a3 += cs[3][d] * wv;
    }
    #pragma unroll
    for (int o = 16; o; o >>= 1) {
        a0 += __shfl_down_sync(0xffffffffu, a0, o);
        a1 += __shfl_down_sync(0xffffffffu, a1, o);
        a2 += __shfl_down_sync(0xffffffffu, a2, o);
        a3 += __shfl_down_sync(0xffffffffu, a3, o);
    }
    if (lane == 0) {
        g_ctxlat[0 * (NH * NK) + h * NK + k] = a0;
        g_ctxlat[1 * (NH * NK) + h * NK + k] = a1;
        g_ctxlat[2 * (NH * NK) + h * NK + k] = a2;
        g_ctxlat[3 * (NH * NK) + h * NK + k] = a3;
    }
}

extern "C" void kernel_launch(void* const* d_in, const int* in_sizes, int n_in,
                              void* d_out, int out_size) {
    const float* hidden_q = (const float*)d_in[0];
    const float* kv_c     = (const float*)d_in[1];
    const float* Wq       = (const float*)d_in[2];
    const float* w_kc_q   = (const float*)d_in[3];
    const float* w_kc_kv  = (const float*)d_in[4];
    const float* W_qr     = (const float*)d_in[5];
    const float* W_kr     = (const float*)d_in[6];
    const float* Wout     = (const float*)d_in[7];
    float* out = (float*)d_out;

    void* qhk_p = nullptr;
    void* ctxlat_p = nullptr;
    cudaGetSymbolAddress(&qhk_p, g_qhk);
    cudaGetSymbolAddress(&ctxlat_p, g_ctxlat);

    k_init_invf<<<1, 256>>>();
    k_rope<<<NB * NL, 256>>>(kv_c);

    // query chain
    k_gemv4<DIMQ, 1792><<<(NH * NK) / 8, 256>>>(Wq, hidden_q, (float*)qhk_p, NH * NK);
    k_qbig3<<<dim3(NH, 2, 4), 192>>>(w_kc_q);
    k_qbig_red<<<(NB * NH * DCQ) / 1024, 256>>>();
    k_qr<<<NH, 256>>>(W_qr);
    k_vq<<<NH, 256>>>(W_kr);

    // attention
    k_scores<<<dim3(NL / 32, NB), 256>>>();
    k_softmax<<<NB * NH, 256>>>();
    k_ctx<<<dim3(32, NH / 32, NB), 256>>>();
    k_ctx_red<<<(NB * NH * DC) / 256, 256>>>();

    // output chain
    k_ctxlat<<<dim3(NH, NK / 8), 256>>>(w_kc_kv);
    k_gemv4<NH * NK, 2048><<<DIMQ / 8, 256>>>(Wout, (const float*)ctxlat_p, out, DIMQ);
}